// round 11
// baseline (speedup 1.0000x reference)
#include <cuda_runtime.h>
#include <cuda_fp16.h>
#include <cstdint>

// ---------------------------------------------------------------------------
// RecurrentGCN (GCLSTM + MLP head).
// Gates: persistent fp16 mma kernel (round-8 validated, at legacy-HMMA floor).
// MLP:   persistent fp16 mma kernel, resident weights, double-buffered A.
// d_out: out[N] | h_new[N,128] | c_new[N,128]
// ---------------------------------------------------------------------------

typedef unsigned long long ull;

__device__ __half g_Bph[73728];
__device__ float  g_bias[512];
__device__ __half g_W1f[8192];
__device__ __half g_W2f[4096];

// ---------------- helpers --------------------------------------------------
__device__ __forceinline__ uint32_t s2u(const void* p) {
    uint32_t a;
    asm("{ .reg .u64 t; cvta.to.shared.u64 t, %1; cvt.u32.u64 %0, t; }"
        : "=r"(a) : "l"(p));
    return a;
}
__device__ __forceinline__ void mma16(float& d0, float& d1, float& d2, float& d3,
                                      uint32_t a0, uint32_t a1, uint32_t a2,
                                      uint32_t a3, uint32_t b0, uint32_t b1) {
    asm volatile(
        "mma.sync.aligned.m16n8k16.row.col.f32.f16.f16.f32 "
        "{%0,%1,%2,%3},{%4,%5,%6,%7},{%8,%9},{%0,%1,%2,%3};"
        : "+f"(d0), "+f"(d1), "+f"(d2), "+f"(d3)
        : "r"(a0), "r"(a1), "r"(a2), "r"(a3), "r"(b0), "r"(b1));
}
__device__ __forceinline__ void ldm4(uint32_t& r0, uint32_t& r1, uint32_t& r2,
                                     uint32_t& r3, uint32_t addr) {
    asm volatile("ldmatrix.sync.aligned.m8n8.x4.shared.b16 {%0,%1,%2,%3}, [%4];"
                 : "=r"(r0), "=r"(r1), "=r"(r2), "=r"(r3) : "r"(addr));
}
__device__ __forceinline__ float sigm(float v) {
    return __fdividef(1.f, 1.f + __expf(-v));
}
__device__ __forceinline__ float tanhv(float v) {
    v = fminf(fmaxf(v, -20.f), 20.f);
    float e = __expf(-2.f * v);
    return __fdividef(1.f - e, 1.f + e);
}
__device__ __forceinline__ uint32_t f2h2(float a, float b) {
    __half2 h = __floats2half2_rn(a, b);
    return *(uint32_t*)&h;
}

// ---------------------------------------------------------------------------
// Pack kernel (validated).
// ---------------------------------------------------------------------------
__global__ void pack_kernel(
    const float* __restrict__ Wi, const float* __restrict__ Wf,
    const float* __restrict__ Wc, const float* __restrict__ Wo,
    const float* __restrict__ Ci, const float* __restrict__ Cf,
    const float* __restrict__ Cc, const float* __restrict__ Co,
    const float* __restrict__ cbi, const float* __restrict__ cbf,
    const float* __restrict__ cbc, const float* __restrict__ cbo,
    const float* __restrict__ bi, const float* __restrict__ bf,
    const float* __restrict__ bc, const float* __restrict__ bo,
    const float* __restrict__ w1, const float* __restrict__ w2)
{
    int idx = blockIdx.x * blockDim.x + threadIdx.x;
    if (idx < 73728) {
        int hh   = idx & 1;
        int r    = (idx >> 1) & 1;
        int lane = (idx >> 2) & 31;
        int t    = (idx >> 7) & 15;
        int wg   = (idx >> 11) & 3;
        int s    = idx >> 13;
        int k    = s * 16 + (lane & 3) * 2 + r * 8 + hh;
        int pcol = wg * 128 + t * 8 + (lane >> 2);
        int j = pcol >> 2, g = pcol & 3;
        const float* W = (g == 0) ? Wi : (g == 1) ? Wf : (g == 2) ? Wc : Wo;
        const float* C = (g == 0) ? Ci : (g == 1) ? Cf : (g == 2) ? Cc : Co;
        float v = (k < 16) ? W[k * 128 + j] : C[(k - 16) * 128 + j];
        g_Bph[idx] = __float2half_rn(v);
    } else if (idx < 74240) {
        int col = idx - 73728;
        int g = col >> 7, j = col & 127;
        const float* cb = (g == 0) ? cbi : (g == 1) ? cbf : (g == 2) ? cbc : cbo;
        const float* bb = (g == 0) ? bi  : (g == 1) ? bf  : (g == 2) ? bc  : bo;
        g_bias[col] = cb[j] + bb[j];
    } else if (idx < 74240 + 8192) {
        int i = idx - 74240;
        int hh = i & 1, r = (i >> 1) & 1, lane = (i >> 2) & 31;
        int t = (i >> 7) & 7, s = (i >> 10) & 7;
        int k = s * 16 + (lane & 3) * 2 + r * 8 + hh;
        int col = t * 8 + (lane >> 2);
        g_W1f[i] = __float2half_rn(w1[k * 64 + col]);
    } else if (idx < 74240 + 8192 + 4096) {
        int i = idx - 74240 - 8192;
        int hh = i & 1, r = (i >> 1) & 1, lane = (i >> 2) & 31;
        int t = (i >> 7) & 7, s = (i >> 10) & 3;
        int k = s * 16 + (lane & 3) * 2 + r * 8 + hh;
        int col = t * 8 + (lane >> 2);
        g_W2f[i] = __float2half_rn(w2[k * 64 + col]);
    }
}

// ---------------------------------------------------------------------------
// Persistent gates kernel (round-8 validated).
// ---------------------------------------------------------------------------
#define GA_A0    0
#define GA_A1    19456
#define GA_SB    38912
#define GA_BIAS  112640
#define GA_PEEP  113664
#define GATES_SMEM_BYTES 114432

__device__ __forceinline__ void stageA(char* dst, const float4* x4,
                                       const float4* h4, int row0, int N,
                                       int tid) {
    #pragma unroll
    for (int ii = 0; ii < 5; ++ii) {
        int i = tid + ii * 256;
        if (i < 1152) {
            int row = i / 18, ch = i % 18;
            int grow = row0 + row; if (grow >= N) grow = N - 1;
            float4 v0, v1;
            if (ch < 2) {
                v0 = x4[(size_t)grow * 4 + ch * 2];
                v1 = x4[(size_t)grow * 4 + ch * 2 + 1];
            } else {
                v0 = h4[(size_t)grow * 32 + ch * 2 - 4];
                v1 = h4[(size_t)grow * 32 + ch * 2 - 3];
            }
            uint4 o;
            o.x = f2h2(v0.x, v0.y); o.y = f2h2(v0.z, v0.w);
            o.z = f2h2(v1.x, v1.y); o.w = f2h2(v1.z, v1.w);
            *(uint4*)(dst + row * 304 + ch * 16) = o;
        }
    }
}

__global__ __launch_bounds__(256, 2)
void gates_mma(const float* __restrict__ x, const float* __restrict__ h,
               const float* __restrict__ c,
               const float* __restrict__ wci, const float* __restrict__ wcf,
               const float* __restrict__ wco,
               float* __restrict__ outh, float* __restrict__ outc,
               int N, int nSlab)
{
    extern __shared__ char sm[];
    const uint32_t* sBu = (const uint32_t*)(sm + GA_SB);
    float* sBias = (float*)(sm + GA_BIAS);
    float* sPeep = (float*)(sm + GA_PEEP);

    const int tid   = threadIdx.x;
    const int lane  = tid & 31;
    const int wid   = tid >> 5;
    const int warpM = wid >> 2;
    const int warpN = wid & 3;
    const int wgl   = warpN >> 1;
    const int t0    = (warpN & 1) * 8;
    const int g4    = lane >> 2;
    const int tg    = lane & 3;
    const int cH    = blockIdx.x & 1;
    const int slab0 = blockIdx.x >> 1;

    const float4* x4 = (const float4*)x;
    const float4* h4 = (const float4*)h;

    {
        const uint4* src = (const uint4*)g_Bph;
        uint4* dst = (uint4*)(sm + GA_SB);
        #pragma unroll
        for (int ii = 0; ii < 18; ++ii) {
            int i = tid + ii * 256;
            int s = i >> 9, rem = i & 511;
            dst[s * 512 + rem] = src[(s * 4 + cH * 2) * 256 + rem];
        }
        int g = tid >> 6, jl = tid & 63;
        sBias[tid] = g_bias[g * 128 + cH * 64 + jl];
        if (tid < 192) {
            const float* P = (g == 0) ? wci : (g == 1) ? wcf : wco;
            sPeep[tid] = P[cH * 64 + jl];
        }
    }
    if (slab0 >= nSlab) return;

    stageA(sm + GA_A0, x4, h4, slab0 * 64, N, tid);
    __syncthreads();

    const int lrow = lane & 15;
    const int lkof = (lane >> 4) * 8;
    const uint32_t aOff = (uint32_t)(warpM * 32 + lrow) * 304 + lkof * 2;
    const uint32_t aB0 = s2u(sm + GA_A0) + aOff;
    const uint32_t aB1 = s2u(sm + GA_A1) + aOff;

    int buf = 0;
    for (int sl = slab0; sl < nSlab; sl += 148, buf ^= 1) {
        const int row0 = sl * 64;

        float4 cpre[4];
        #pragma unroll
        for (int ii = 0; ii < 4; ++ii) {
            int i = tid + ii * 256;
            int r = i >> 4, q = i & 15;
            int grow = row0 + r; if (grow >= N) grow = N - 1;
            cpre[ii] = ((const float4*)c)[(size_t)grow * 32 + cH * 16 + q];
        }
        if (sl + 148 < nSlab)
            stageA(sm + (buf ? GA_A0 : GA_A1), x4, h4, (sl + 148) * 64, N, tid);

        const uint32_t aBase = buf ? aB1 : aB0;
        float acc[2][8][4];
        #pragma unroll
        for (int m = 0; m < 2; ++m)
            #pragma unroll
            for (int t = 0; t < 8; ++t)
                #pragma unroll
                for (int e = 0; e < 4; ++e) acc[m][t][e] = 0.f;

        #pragma unroll
        for (int s = 0; s < 9; ++s) {
            uint32_t a[2][4];
            ldm4(a[0][0], a[0][1], a[0][2], a[0][3], aBase + s * 32);
            ldm4(a[1][0], a[1][1], a[1][2], a[1][3], aBase + s * 32 + 16 * 304);
            const uint32_t* bb = sBu + ((s * 2 + wgl) * 16 + t0) * 64 + lane * 2;
            #pragma unroll
            for (int t = 0; t < 8; ++t) {
                uint32_t b0 = bb[t * 64], b1 = bb[t * 64 + 1];
                mma16(acc[0][t][0], acc[0][t][1], acc[0][t][2], acc[0][t][3],
                      a[0][0], a[0][1], a[0][2], a[0][3], b0, b1);
                mma16(acc[1][t][0], acc[1][t][1], acc[1][t][2], acc[1][t][3],
                      a[1][0], a[1][1], a[1][2], a[1][3], b0, b1);
            }
        }
        __syncthreads();

        float* U = (float*)(sm + (buf ? GA_A1 : GA_A0));

        #pragma unroll
        for (int ii = 0; ii < 4; ++ii) {
            int i = tid + ii * 256;
            int r = i >> 4, q = i & 15;
            *(float4*)&U[r * 68 + q * 4] = cpre[ii];
        }
        __syncthreads();

        float hnreg[16];
        #pragma unroll
        for (int m = 0; m < 2; ++m) {
            const int rbase = warpM * 32 + m * 16 + g4;
            #pragma unroll
            for (int t = 0; t < 8; ++t) {
                float c0 = acc[m][t][0], c1 = acc[m][t][1];
                float c2 = acc[m][t][2], c3 = acc[m][t][3];
                float o0 = __shfl_xor_sync(0xffffffffu, c0, 1);
                float o1 = __shfl_xor_sync(0xffffffffu, c1, 1);
                float o2 = __shfl_xor_sync(0xffffffffu, c2, 1);
                float o3 = __shfl_xor_sync(0xffffffffu, c3, 1);
                int jl = wgl * 32 + (t0 + t) * 2 + (tg >> 1);
                int odd = lane & 1;
                int r = odd ? rbase + 8 : rbase;
                float gi = odd ? o2 : c0;
                float gf = odd ? o3 : c1;
                float gc = odd ? c2 : o0;
                float go = odd ? c3 : o1;
                float co = U[r * 68 + jl];
                float pi = gi + sBias[jl]       + sPeep[jl] * co;
                float pf = gf + sBias[64 + jl]  + sPeep[64 + jl] * co;
                float pc = gc + sBias[128 + jl];
                float po = go + sBias[192 + jl];
                float iv = sigm(pi), fv = sigm(pf), tv = tanhv(pc);
                float cn = fv * co + iv * tv;
                float ov = sigm(po + sPeep[128 + jl] * cn);
                U[r * 68 + jl] = cn;
                hnreg[m * 8 + t] = ov * tanhv(cn);
            }
        }
        __syncthreads();

        #pragma unroll
        for (int ii = 0; ii < 4; ++ii) {
            int i = tid + ii * 256;
            int r = i >> 4, q = i & 15;
            int grow = row0 + r;
            if (grow < N)
                ((float4*)outc)[(size_t)grow * 32 + cH * 16 + q] =
                    *(float4*)&U[r * 68 + q * 4];
        }
        __syncthreads();

        #pragma unroll
        for (int m = 0; m < 2; ++m) {
            const int rbase = warpM * 32 + m * 16 + g4;
            #pragma unroll
            for (int t = 0; t < 8; ++t) {
                int jl = wgl * 32 + (t0 + t) * 2 + (tg >> 1);
                int r = (lane & 1) ? rbase + 8 : rbase;
                U[r * 68 + jl] = hnreg[m * 8 + t];
            }
        }
        __syncthreads();
        #pragma unroll
        for (int ii = 0; ii < 4; ++ii) {
            int i = tid + ii * 256;
            int r = i >> 4, q = i & 15;
            int grow = row0 + r;
            if (grow < N)
                ((float4*)outh)[(size_t)grow * 32 + cH * 16 + q] =
                    *(float4*)&U[r * 68 + q * 4];
        }
        __syncthreads();
    }
}

// ---------------------------------------------------------------------------
// Persistent MLP kernel: resident weights, double-buffered A1, register
// prefetch of next slab's h. smem (bytes):
//   sA1a @0 (17408), sA1b @17408 (17408), sW1f @34816 (16384),
//   sW2f @51200 (8192), sA2 @59392 (9216), sB @68608 (768). Total 69376.
// Layer-2 output U = retiring A1 buffer (64 x 68 f = 17408 B).
// ---------------------------------------------------------------------------
#define ML_A1A  0
#define ML_A1B  17408
#define ML_W1F  34816
#define ML_W2F  51200
#define ML_A2   59392
#define ML_SB   68608
#define MLP_SMEM_BYTES 69376

__global__ __launch_bounds__(256)
void mlp_mma(const float* __restrict__ hsrc,
             const float* __restrict__ b1, const float* __restrict__ b2,
             const float* __restrict__ w3, const float* __restrict__ b3,
             float* __restrict__ out, int N, int nSlab)
{
    extern __shared__ char sm[];
    const uint32_t* sW1u = (const uint32_t*)(sm + ML_W1F);
    const uint32_t* sW2u = (const uint32_t*)(sm + ML_W2F);
    char* sA2 = sm + ML_A2;
    float* sB1 = (float*)(sm + ML_SB);
    float* sB2 = sB1 + 64;
    float* sW3 = sB1 + 128;

    const int tid   = threadIdx.x;
    const int lane  = tid & 31;
    const int wid   = tid >> 5;
    const int warpM = wid >> 2;
    const int warpN = wid & 3;
    const int g4    = lane >> 2;
    const int tg    = lane & 3;
    const int slab0 = blockIdx.x;

    // ---- One-time: weight fragments + vectors -----------------------------
    {
        const uint4* s1 = (const uint4*)g_W1f;
        uint4* d1 = (uint4*)(sm + ML_W1F);
        #pragma unroll
        for (int ii = 0; ii < 4; ++ii) d1[tid + ii * 256] = s1[tid + ii * 256];
        const uint4* s2 = (const uint4*)g_W2f;
        uint4* d2 = (uint4*)(sm + ML_W2F);
        #pragma unroll
        for (int ii = 0; ii < 2; ++ii) d2[tid + ii * 256] = s2[tid + ii * 256];
    }
    if (tid < 64) { sB1[tid] = b1[tid]; sB2[tid] = b2[tid]; sW3[tid] = w3[tid]; }
    if (slab0 >= nSlab) return;

    const int lrow = lane & 15;
    const int lkof = (lane >> 4) * 8;
    const uint32_t a2B = s2u(sA2) + (uint32_t)(warpM * 32 + lrow) * 144 + lkof * 2;

    // ---- Prefetch first slab's h into registers ---------------------------
    float4 hpre[4][2];
    {
        const int row0 = slab0 * 64;
        #pragma unroll
        for (int ii = 0; ii < 4; ++ii) {
            int i = tid + ii * 256;
            int row = i >> 4, ch = i & 15;
            int grow = row0 + row; if (grow >= N) grow = N - 1;
            const float4* p = (const float4*)&hsrc[(size_t)grow * 128 + ch * 8];
            hpre[ii][0] = p[0]; hpre[ii][1] = p[1];
        }
    }

    int buf = 0;
    for (int sl = slab0; sl < nSlab; sl += 296, buf ^= 1) {
        const int row0 = sl * 64;
        char* sA1 = sm + (buf ? ML_A1B : ML_A1A);

        // ---- relu + fp16 convert from prefetched registers ----------------
        #pragma unroll
        for (int ii = 0; ii < 4; ++ii) {
            int i = tid + ii * 256;
            int row = i >> 4, ch = i & 15;
            float4 v0 = hpre[ii][0], v1 = hpre[ii][1];
            v0.x = fmaxf(v0.x, 0.f); v0.y = fmaxf(v0.y, 0.f);
            v0.z = fmaxf(v0.z, 0.f); v0.w = fmaxf(v0.w, 0.f);
            v1.x = fmaxf(v1.x, 0.f); v1.y = fmaxf(v1.y, 0.f);
            v1.z = fmaxf(v1.z, 0.f); v1.w = fmaxf(v1.w, 0.f);
            uint4 o;
            o.x = f2h2(v0.x, v0.y); o.y = f2h2(v0.z, v0.w);
            o.z = f2h2(v1.x, v1.y); o.w = f2h2(v1.z, v1.w);
            *(uint4*)(sA1 + row * 272 + ch * 16) = o;
        }
        __syncthreads();

        // ---- Prefetch next slab (latency hides under both mma stages) -----
        if (sl + 296 < nSlab) {
            const int nrow0 = (sl + 296) * 64;
            #pragma unroll
            for (int ii = 0; ii < 4; ++ii) {
                int i = tid + ii * 256;
                int row = i >> 4, ch = i & 15;
                int grow = nrow0 + row; if (grow >= N) grow = N - 1;
                const float4* p = (const float4*)&hsrc[(size_t)grow * 128 + ch * 8];
                hpre[ii][0] = p[0]; hpre[ii][1] = p[1];
            }
        }

        // ---- Layer 1: 128 -> 64 (8 k-steps) -------------------------------
        {
            const uint32_t aB = s2u(sA1) + (uint32_t)(warpM * 32 + lrow) * 272 + lkof * 2;
            float acc[2][2][4];
            #pragma unroll
            for (int m = 0; m < 2; ++m)
                #pragma unroll
                for (int t = 0; t < 2; ++t)
                    #pragma unroll
                    for (int e = 0; e < 4; ++e) acc[m][t][e] = 0.f;
            #pragma unroll
            for (int s = 0; s < 8; ++s) {
                uint32_t a[2][4];
                ldm4(a[0][0], a[0][1], a[0][2], a[0][3], aB + s * 32);
                ldm4(a[1][0], a[1][1], a[1][2], a[1][3], aB + s * 32 + 16 * 272);
                #pragma unroll
                for (int t = 0; t < 2; ++t) {
                    const uint32_t* bb = sW1u + ((s * 8 + warpN * 2 + t) * 32 + lane) * 2;
                    uint32_t b0 = bb[0], b1v = bb[1];
                    mma16(acc[0][t][0], acc[0][t][1], acc[0][t][2], acc[0][t][3],
                          a[0][0], a[0][1], a[0][2], a[0][3], b0, b1v);
                    mma16(acc[1][t][0], acc[1][t][1], acc[1][t][2], acc[1][t][3],
                          a[1][0], a[1][1], a[1][2], a[1][3], b0, b1v);
                }
            }
            #pragma unroll
            for (int t = 0; t < 2; ++t) {
                int col = (warpN * 2 + t) * 8 + tg * 2;
                float ba = sB1[col], bb2 = sB1[col + 1];
                #pragma unroll
                for (int m = 0; m < 2; ++m) {
                    int r = warpM * 32 + m * 16 + g4;
                    float v0 = fmaxf(acc[m][t][0] + ba, 0.f);
                    float v1 = fmaxf(acc[m][t][1] + bb2, 0.f);
                    float v2 = fmaxf(acc[m][t][2] + ba, 0.f);
                    float v3 = fmaxf(acc[m][t][3] + bb2, 0.f);
                    *(uint32_t*)(sA2 + r * 144 + col * 2) = f2h2(v0, v1);
                    *(uint32_t*)(sA2 + (r + 8) * 144 + col * 2) = f2h2(v2, v3);
                }
            }
        }
        __syncthreads();

        // ---- Layer 2: 64 -> 64 (4 k-steps); U = retiring A1 ---------------
        float* U = (float*)sA1;
        {
            float acc[2][2][4];
            #pragma unroll
            for (int m = 0; m < 2; ++m)
                #pragma unroll
                for (int t = 0; t < 2; ++t)
                    #pragma unroll
                    for (int e = 0; e < 4; ++e) acc[m][t][e] = 0.f;
            #pragma unroll
            for (int s = 0; s < 4; ++s) {
                uint32_t a[2][4];
                ldm4(a[0][0], a[0][1], a[0][2], a[0][3], a2B + s * 32);
                ldm4(a[1][0], a[1][1], a[1][2], a[1][3], a2B + s * 32 + 16 * 144);
                #pragma unroll
                for (int t = 0; t < 2; ++t) {
                    const uint32_t* bb = sW2u + ((s * 8 + warpN * 2 + t) * 32 + lane) * 2;
                    uint32_t b0 = bb[0], b1v = bb[1];
                    mma16(acc[0][t][0], acc[0][t][1], acc[0][t][2], acc[0][t][3],
                          a[0][0], a[0][1], a[0][2], a[0][3], b0, b1v);
                    mma16(acc[1][t][0], acc[1][t][1], acc[1][t][2], acc[1][t][3],
                          a[1][0], a[1][1], a[1][2], a[1][3], b0, b1v);
                }
            }
            __syncthreads();   // A1 reads (none) / ensure sA1 free: layer1 done
            #pragma unroll
            for (int t = 0; t < 2; ++t) {
                int col = (warpN * 2 + t) * 8 + tg * 2;
                float ba = sB2[col], bb2 = sB2[col + 1];
                #pragma unroll
                for (int m = 0; m < 2; ++m) {
                    int r = warpM * 32 + m * 16 + g4;
                    *(float2*)&U[r * 68 + col] =
                        make_float2(fmaxf(acc[m][t][0] + ba, 0.f),
                                    fmaxf(acc[m][t][1] + bb2, 0.f));
                    *(float2*)&U[(r + 8) * 68 + col] =
                        make_float2(fmaxf(acc[m][t][2] + ba, 0.f),
                                    fmaxf(acc[m][t][3] + bb2, 0.f));
                }
            }
        }
        __syncthreads();

        // ---- Layer 3: 64 -> 1 (next STS targets the other A1 buffer,
        //      so no trailing barrier needed before the next iteration) ------
        if (tid < 64) {
            int grow = row0 + tid;
            if (grow < N) {
                float a = b3[0];
                #pragma unroll
                for (int k = 0; k < 64; ++k) a += U[tid * 68 + k] * sW3[k];
                out[grow] = a;
            }
        }
    }
}

// ---------------------------------------------------------------------------
extern "C" void kernel_launch(void* const* d_in, const int* in_sizes, int n_in,
                              void* d_out, int out_size)
{
    const float* x   = (const float*)d_in[0];
    const float* h   = (const float*)d_in[3];
    const float* c   = (const float*)d_in[4];
    const float* Wi  = (const float*)d_in[5];
    const float* Wf  = (const float*)d_in[6];
    const float* Wc  = (const float*)d_in[7];
    const float* Wo  = (const float*)d_in[8];
    const float* Ci  = (const float*)d_in[9];
    const float* Cf  = (const float*)d_in[10];
    const float* Cc  = (const float*)d_in[11];
    const float* Co  = (const float*)d_in[12];
    const float* cbi = (const float*)d_in[13];
    const float* cbf = (const float*)d_in[14];
    const float* cbc = (const float*)d_in[15];
    const float* cbo = (const float*)d_in[16];
    const float* wci = (const float*)d_in[17];
    const float* wcf = (const float*)d_in[18];
    const float* wco = (const float*)d_in[19];
    const float* bi  = (const float*)d_in[20];
    const float* bf  = (const float*)d_in[21];
    const float* bc  = (const float*)d_in[22];
    const float* bo  = (const float*)d_in[23];
    const float* w1  = (const float*)d_in[24];
    const float* b1  = (const float*)d_in[25];
    const float* w2  = (const float*)d_in[26];
    const float* b2  = (const float*)d_in[27];
    const float* w3  = (const float*)d_in[28];
    const float* b3  = (const float*)d_in[29];

    const int N = in_sizes[3] / 128;
    const int nSlab = (N + 63) / 64;

    float* out  = (float*)d_out;
    float* outh = out + N;
    float* outc = outh + (size_t)N * 128;

    pack_kernel<<<(74240 + 8192 + 4096 + 255) / 256, 256>>>(
        Wi, Wf, Wc, Wo, Ci, Cf, Cc, Co,
        cbi, cbf, cbc, cbo, bi, bf, bc, bo, w1, w2);

    cudaFuncSetAttribute(gates_mma,
                         cudaFuncAttributeMaxDynamicSharedMemorySize,
                         GATES_SMEM_BYTES);
    gates_mma<<<296, 256, GATES_SMEM_BYTES>>>(
        x, h, c, wci, wcf, wco, outh, outc, N, nSlab);

    cudaFuncSetAttribute(mlp_mma,
                         cudaFuncAttributeMaxDynamicSharedMemorySize,
                         MLP_SMEM_BYTES);
    mlp_mma<<<296, 256, MLP_SMEM_BYTES>>>(
        outh, b1, b2, w3, b3, out, N, nSlab);
}

// round 13
// speedup vs baseline: 1.5044x; 1.5044x over previous
#include <cuda_runtime.h>
#include <cuda_fp16.h>
#include <cstdint>

// ---------------------------------------------------------------------------
// RecurrentGCN (GCLSTM + MLP head).
// Gates: persistent fp16 mma kernel (round-8 validated, at legacy-HMMA floor).
// MLP:   persistent-lite fp16 mma kernel — weights resident per CTA, per-slab
//        R8-validated staging (low register pressure, forced 2 CTAs/SM).
// d_out: out[N] | h_new[N,128] | c_new[N,128]
// ---------------------------------------------------------------------------

typedef unsigned long long ull;

__device__ __half g_Bph[73728];
__device__ float  g_bias[512];
__device__ __half g_W1f[8192];
__device__ __half g_W2f[4096];

// ---------------- helpers --------------------------------------------------
__device__ __forceinline__ uint32_t s2u(const void* p) {
    uint32_t a;
    asm("{ .reg .u64 t; cvta.to.shared.u64 t, %1; cvt.u32.u64 %0, t; }"
        : "=r"(a) : "l"(p));
    return a;
}
__device__ __forceinline__ void mma16(float& d0, float& d1, float& d2, float& d3,
                                      uint32_t a0, uint32_t a1, uint32_t a2,
                                      uint32_t a3, uint32_t b0, uint32_t b1) {
    asm volatile(
        "mma.sync.aligned.m16n8k16.row.col.f32.f16.f16.f32 "
        "{%0,%1,%2,%3},{%4,%5,%6,%7},{%8,%9},{%0,%1,%2,%3};"
        : "+f"(d0), "+f"(d1), "+f"(d2), "+f"(d3)
        : "r"(a0), "r"(a1), "r"(a2), "r"(a3), "r"(b0), "r"(b1));
}
__device__ __forceinline__ void ldm4(uint32_t& r0, uint32_t& r1, uint32_t& r2,
                                     uint32_t& r3, uint32_t addr) {
    asm volatile("ldmatrix.sync.aligned.m8n8.x4.shared.b16 {%0,%1,%2,%3}, [%4];"
                 : "=r"(r0), "=r"(r1), "=r"(r2), "=r"(r3) : "r"(addr));
}
__device__ __forceinline__ float sigm(float v) {
    return __fdividef(1.f, 1.f + __expf(-v));
}
__device__ __forceinline__ float tanhv(float v) {
    v = fminf(fmaxf(v, -20.f), 20.f);
    float e = __expf(-2.f * v);
    return __fdividef(1.f - e, 1.f + e);
}
__device__ __forceinline__ uint32_t f2h2(float a, float b) {
    __half2 h = __floats2half2_rn(a, b);
    return *(uint32_t*)&h;
}

// ---------------------------------------------------------------------------
// Pack kernel (validated).
// ---------------------------------------------------------------------------
__global__ void pack_kernel(
    const float* __restrict__ Wi, const float* __restrict__ Wf,
    const float* __restrict__ Wc, const float* __restrict__ Wo,
    const float* __restrict__ Ci, const float* __restrict__ Cf,
    const float* __restrict__ Cc, const float* __restrict__ Co,
    const float* __restrict__ cbi, const float* __restrict__ cbf,
    const float* __restrict__ cbc, const float* __restrict__ cbo,
    const float* __restrict__ bi, const float* __restrict__ bf,
    const float* __restrict__ bc, const float* __restrict__ bo,
    const float* __restrict__ w1, const float* __restrict__ w2)
{
    int idx = blockIdx.x * blockDim.x + threadIdx.x;
    if (idx < 73728) {
        int hh   = idx & 1;
        int r    = (idx >> 1) & 1;
        int lane = (idx >> 2) & 31;
        int t    = (idx >> 7) & 15;
        int wg   = (idx >> 11) & 3;
        int s    = idx >> 13;
        int k    = s * 16 + (lane & 3) * 2 + r * 8 + hh;
        int pcol = wg * 128 + t * 8 + (lane >> 2);
        int j = pcol >> 2, g = pcol & 3;
        const float* W = (g == 0) ? Wi : (g == 1) ? Wf : (g == 2) ? Wc : Wo;
        const float* C = (g == 0) ? Ci : (g == 1) ? Cf : (g == 2) ? Cc : Co;
        float v = (k < 16) ? W[k * 128 + j] : C[(k - 16) * 128 + j];
        g_Bph[idx] = __float2half_rn(v);
    } else if (idx < 74240) {
        int col = idx - 73728;
        int g = col >> 7, j = col & 127;
        const float* cb = (g == 0) ? cbi : (g == 1) ? cbf : (g == 2) ? cbc : cbo;
        const float* bb = (g == 0) ? bi  : (g == 1) ? bf  : (g == 2) ? bc  : bo;
        g_bias[col] = cb[j] + bb[j];
    } else if (idx < 74240 + 8192) {
        int i = idx - 74240;
        int hh = i & 1, r = (i >> 1) & 1, lane = (i >> 2) & 31;
        int t = (i >> 7) & 7, s = (i >> 10) & 7;
        int k = s * 16 + (lane & 3) * 2 + r * 8 + hh;
        int col = t * 8 + (lane >> 2);
        g_W1f[i] = __float2half_rn(w1[k * 64 + col]);
    } else if (idx < 74240 + 8192 + 4096) {
        int i = idx - 74240 - 8192;
        int hh = i & 1, r = (i >> 1) & 1, lane = (i >> 2) & 31;
        int t = (i >> 7) & 7, s = (i >> 10) & 3;
        int k = s * 16 + (lane & 3) * 2 + r * 8 + hh;
        int col = t * 8 + (lane >> 2);
        g_W2f[i] = __float2half_rn(w2[k * 64 + col]);
    }
}

// ---------------------------------------------------------------------------
// Persistent gates kernel (round-8 validated, unchanged).
// ---------------------------------------------------------------------------
#define GA_A0    0
#define GA_A1    19456
#define GA_SB    38912
#define GA_BIAS  112640
#define GA_PEEP  113664
#define GATES_SMEM_BYTES 114432

__device__ __forceinline__ void stageA(char* dst, const float4* x4,
                                       const float4* h4, int row0, int N,
                                       int tid) {
    #pragma unroll
    for (int ii = 0; ii < 5; ++ii) {
        int i = tid + ii * 256;
        if (i < 1152) {
            int row = i / 18, ch = i % 18;
            int grow = row0 + row; if (grow >= N) grow = N - 1;
            float4 v0, v1;
            if (ch < 2) {
                v0 = x4[(size_t)grow * 4 + ch * 2];
                v1 = x4[(size_t)grow * 4 + ch * 2 + 1];
            } else {
                v0 = h4[(size_t)grow * 32 + ch * 2 - 4];
                v1 = h4[(size_t)grow * 32 + ch * 2 - 3];
            }
            uint4 o;
            o.x = f2h2(v0.x, v0.y); o.y = f2h2(v0.z, v0.w);
            o.z = f2h2(v1.x, v1.y); o.w = f2h2(v1.z, v1.w);
            *(uint4*)(dst + row * 304 + ch * 16) = o;
        }
    }
}

__global__ __launch_bounds__(256, 2)
void gates_mma(const float* __restrict__ x, const float* __restrict__ h,
               const float* __restrict__ c,
               const float* __restrict__ wci, const float* __restrict__ wcf,
               const float* __restrict__ wco,
               float* __restrict__ outh, float* __restrict__ outc,
               int N, int nSlab)
{
    extern __shared__ char sm[];
    const uint32_t* sBu = (const uint32_t*)(sm + GA_SB);
    float* sBias = (float*)(sm + GA_BIAS);
    float* sPeep = (float*)(sm + GA_PEEP);

    const int tid   = threadIdx.x;
    const int lane  = tid & 31;
    const int wid   = tid >> 5;
    const int warpM = wid >> 2;
    const int warpN = wid & 3;
    const int wgl   = warpN >> 1;
    const int t0    = (warpN & 1) * 8;
    const int g4    = lane >> 2;
    const int tg    = lane & 3;
    const int cH    = blockIdx.x & 1;
    const int slab0 = blockIdx.x >> 1;

    const float4* x4 = (const float4*)x;
    const float4* h4 = (const float4*)h;

    {
        const uint4* src = (const uint4*)g_Bph;
        uint4* dst = (uint4*)(sm + GA_SB);
        #pragma unroll
        for (int ii = 0; ii < 18; ++ii) {
            int i = tid + ii * 256;
            int s = i >> 9, rem = i & 511;
            dst[s * 512 + rem] = src[(s * 4 + cH * 2) * 256 + rem];
        }
        int g = tid >> 6, jl = tid & 63;
        sBias[tid] = g_bias[g * 128 + cH * 64 + jl];
        if (tid < 192) {
            const float* P = (g == 0) ? wci : (g == 1) ? wcf : wco;
            sPeep[tid] = P[cH * 64 + jl];
        }
    }
    if (slab0 >= nSlab) return;

    stageA(sm + GA_A0, x4, h4, slab0 * 64, N, tid);
    __syncthreads();

    const int lrow = lane & 15;
    const int lkof = (lane >> 4) * 8;
    const uint32_t aOff = (uint32_t)(warpM * 32 + lrow) * 304 + lkof * 2;
    const uint32_t aB0 = s2u(sm + GA_A0) + aOff;
    const uint32_t aB1 = s2u(sm + GA_A1) + aOff;

    int buf = 0;
    for (int sl = slab0; sl < nSlab; sl += 148, buf ^= 1) {
        const int row0 = sl * 64;

        float4 cpre[4];
        #pragma unroll
        for (int ii = 0; ii < 4; ++ii) {
            int i = tid + ii * 256;
            int r = i >> 4, q = i & 15;
            int grow = row0 + r; if (grow >= N) grow = N - 1;
            cpre[ii] = ((const float4*)c)[(size_t)grow * 32 + cH * 16 + q];
        }
        if (sl + 148 < nSlab)
            stageA(sm + (buf ? GA_A0 : GA_A1), x4, h4, (sl + 148) * 64, N, tid);

        const uint32_t aBase = buf ? aB1 : aB0;
        float acc[2][8][4];
        #pragma unroll
        for (int m = 0; m < 2; ++m)
            #pragma unroll
            for (int t = 0; t < 8; ++t)
                #pragma unroll
                for (int e = 0; e < 4; ++e) acc[m][t][e] = 0.f;

        #pragma unroll
        for (int s = 0; s < 9; ++s) {
            uint32_t a[2][4];
            ldm4(a[0][0], a[0][1], a[0][2], a[0][3], aBase + s * 32);
            ldm4(a[1][0], a[1][1], a[1][2], a[1][3], aBase + s * 32 + 16 * 304);
            const uint32_t* bb = sBu + ((s * 2 + wgl) * 16 + t0) * 64 + lane * 2;
            #pragma unroll
            for (int t = 0; t < 8; ++t) {
                uint32_t b0 = bb[t * 64], b1 = bb[t * 64 + 1];
                mma16(acc[0][t][0], acc[0][t][1], acc[0][t][2], acc[0][t][3],
                      a[0][0], a[0][1], a[0][2], a[0][3], b0, b1);
                mma16(acc[1][t][0], acc[1][t][1], acc[1][t][2], acc[1][t][3],
                      a[1][0], a[1][1], a[1][2], a[1][3], b0, b1);
            }
        }
        __syncthreads();

        float* U = (float*)(sm + (buf ? GA_A1 : GA_A0));

        #pragma unroll
        for (int ii = 0; ii < 4; ++ii) {
            int i = tid + ii * 256;
            int r = i >> 4, q = i & 15;
            *(float4*)&U[r * 68 + q * 4] = cpre[ii];
        }
        __syncthreads();

        float hnreg[16];
        #pragma unroll
        for (int m = 0; m < 2; ++m) {
            const int rbase = warpM * 32 + m * 16 + g4;
            #pragma unroll
            for (int t = 0; t < 8; ++t) {
                float c0 = acc[m][t][0], c1 = acc[m][t][1];
                float c2 = acc[m][t][2], c3 = acc[m][t][3];
                float o0 = __shfl_xor_sync(0xffffffffu, c0, 1);
                float o1 = __shfl_xor_sync(0xffffffffu, c1, 1);
                float o2 = __shfl_xor_sync(0xffffffffu, c2, 1);
                float o3 = __shfl_xor_sync(0xffffffffu, c3, 1);
                int jl = wgl * 32 + (t0 + t) * 2 + (tg >> 1);
                int odd = lane & 1;
                int r = odd ? rbase + 8 : rbase;
                float gi = odd ? o2 : c0;
                float gf = odd ? o3 : c1;
                float gc = odd ? c2 : o0;
                float go = odd ? c3 : o1;
                float co = U[r * 68 + jl];
                float pi = gi + sBias[jl]       + sPeep[jl] * co;
                float pf = gf + sBias[64 + jl]  + sPeep[64 + jl] * co;
                float pc = gc + sBias[128 + jl];
                float po = go + sBias[192 + jl];
                float iv = sigm(pi), fv = sigm(pf), tv = tanhv(pc);
                float cn = fv * co + iv * tv;
                float ov = sigm(po + sPeep[128 + jl] * cn);
                U[r * 68 + jl] = cn;
                hnreg[m * 8 + t] = ov * tanhv(cn);
            }
        }
        __syncthreads();

        #pragma unroll
        for (int ii = 0; ii < 4; ++ii) {
            int i = tid + ii * 256;
            int r = i >> 4, q = i & 15;
            int grow = row0 + r;
            if (grow < N)
                ((float4*)outc)[(size_t)grow * 32 + cH * 16 + q] =
                    *(float4*)&U[r * 68 + q * 4];
        }
        __syncthreads();

        #pragma unroll
        for (int m = 0; m < 2; ++m) {
            const int rbase = warpM * 32 + m * 16 + g4;
            #pragma unroll
            for (int t = 0; t < 8; ++t) {
                int jl = wgl * 32 + (t0 + t) * 2 + (tg >> 1);
                int r = (lane & 1) ? rbase + 8 : rbase;
                U[r * 68 + jl] = hnreg[m * 8 + t];
            }
        }
        __syncthreads();
        #pragma unroll
        for (int ii = 0; ii < 4; ++ii) {
            int i = tid + ii * 256;
            int r = i >> 4, q = i & 15;
            int grow = row0 + r;
            if (grow < N)
                ((float4*)outh)[(size_t)grow * 32 + cH * 16 + q] =
                    *(float4*)&U[r * 68 + q * 4];
        }
        __syncthreads();
    }
}

// ---------------------------------------------------------------------------
// Persistent-lite MLP: R8-validated per-slab body inside a slab loop; weights
// staged once per CTA; forced 2 CTAs/SM. smem layout = R8:
//   sA1 @0 (17408), sW1f @17408 (16384), sW2f @33792 (8192),
//   sA2 @41984 (9216), sL2 @51200 (17408), sB @68608 (768). Total 69376.
// ---------------------------------------------------------------------------
#define ML_A1   0
#define ML_W1F  17408
#define ML_W2F  33792
#define ML_A2   41984
#define ML_L2   51200
#define ML_SB   68608
#define MLP_SMEM_BYTES 69376

__global__ __launch_bounds__(256, 2)
void mlp_mma(const float* __restrict__ hsrc,
             const float* __restrict__ b1, const float* __restrict__ b2,
             const float* __restrict__ w3, const float* __restrict__ b3,
             float* __restrict__ out, int N, int nSlab)
{
    extern __shared__ char sm[];
    char* sA1 = sm + ML_A1;
    const uint32_t* sW1u = (const uint32_t*)(sm + ML_W1F);
    const uint32_t* sW2u = (const uint32_t*)(sm + ML_W2F);
    char* sA2 = sm + ML_A2;
    float* sL2 = (float*)(sm + ML_L2);
    float* sB1 = (float*)(sm + ML_SB);
    float* sB2 = sB1 + 64;
    float* sW3 = sB1 + 128;

    const int tid   = threadIdx.x;
    const int lane  = tid & 31;
    const int wid   = tid >> 5;
    const int warpM = wid >> 2;
    const int warpN = wid & 3;
    const int g4    = lane >> 2;
    const int tg    = lane & 3;
    const int slab0 = blockIdx.x;

    // ---- One-time: weight fragments + vectors -----------------------------
    {
        const uint4* s1 = (const uint4*)g_W1f;
        uint4* d1 = (uint4*)(sm + ML_W1F);
        #pragma unroll
        for (int ii = 0; ii < 4; ++ii) d1[tid + ii * 256] = s1[tid + ii * 256];
        const uint4* s2 = (const uint4*)g_W2f;
        uint4* d2 = (uint4*)(sm + ML_W2F);
        #pragma unroll
        for (int ii = 0; ii < 2; ++ii) d2[tid + ii * 256] = s2[tid + ii * 256];
    }
    if (tid < 64) { sB1[tid] = b1[tid]; sB2[tid] = b2[tid]; sW3[tid] = w3[tid]; }
    if (slab0 >= nSlab) return;

    const int lrow = lane & 15;
    const int lkof = (lane >> 4) * 8;
    const uint32_t a1B = s2u(sA1) + (uint32_t)(warpM * 32 + lrow) * 272 + lkof * 2;
    const uint32_t a2B = s2u(sA2) + (uint32_t)(warpM * 32 + lrow) * 144 + lkof * 2;

    for (int sl = slab0; sl < nSlab; sl += 296) {
        const int row0 = sl * 64;

        // ---- Stage A1 = relu(h) fp16 (direct LDG->STS, short reg lives) ---
        #pragma unroll
        for (int ii = 0; ii < 4; ++ii) {
            int i = tid + ii * 256;
            int row = i >> 4, ch = i & 15;
            int grow = row0 + row; if (grow >= N) grow = N - 1;
            const float4* p = (const float4*)&hsrc[(size_t)grow * 128 + ch * 8];
            float4 v0 = p[0], v1 = p[1];
            v0.x = fmaxf(v0.x, 0.f); v0.y = fmaxf(v0.y, 0.f);
            v0.z = fmaxf(v0.z, 0.f); v0.w = fmaxf(v0.w, 0.f);
            v1.x = fmaxf(v1.x, 0.f); v1.y = fmaxf(v1.y, 0.f);
            v1.z = fmaxf(v1.z, 0.f); v1.w = fmaxf(v1.w, 0.f);
            uint4 o;
            o.x = f2h2(v0.x, v0.y); o.y = f2h2(v0.z, v0.w);
            o.z = f2h2(v1.x, v1.y); o.w = f2h2(v1.z, v1.w);
            *(uint4*)(sA1 + row * 272 + ch * 16) = o;
        }
        __syncthreads();

        // ---- Layer 1: 128 -> 64 (8 k-steps) -------------------------------
        {
            float acc[2][2][4];
            #pragma unroll
            for (int m = 0; m < 2; ++m)
                #pragma unroll
                for (int t = 0; t < 2; ++t)
                    #pragma unroll
                    for (int e = 0; e < 4; ++e) acc[m][t][e] = 0.f;
            #pragma unroll
            for (int s = 0; s < 8; ++s) {
                uint32_t a[2][4];
                ldm4(a[0][0], a[0][1], a[0][2], a[0][3], a1B + s * 32);
                ldm4(a[1][0], a[1][1], a[1][2], a[1][3], a1B + s * 32 + 16 * 272);
                #pragma unroll
                for (int t = 0; t < 2; ++t) {
                    const uint32_t* bb = sW1u + ((s * 8 + warpN * 2 + t) * 32 + lane) * 2;
                    uint32_t b0 = bb[0], b1v = bb[1];
                    mma16(acc[0][t][0], acc[0][t][1], acc[0][t][2], acc[0][t][3],
                          a[0][0], a[0][1], a[0][2], a[0][3], b0, b1v);
                    mma16(acc[1][t][0], acc[1][t][1], acc[1][t][2], acc[1][t][3],
                          a[1][0], a[1][1], a[1][2], a[1][3], b0, b1v);
                }
            }
            #pragma unroll
            for (int t = 0; t < 2; ++t) {
                int col = (warpN * 2 + t) * 8 + tg * 2;
                float ba = sB1[col], bb2 = sB1[col + 1];
                #pragma unroll
                for (int m = 0; m < 2; ++m) {
                    int r = warpM * 32 + m * 16 + g4;
                    float v0 = fmaxf(acc[m][t][0] + ba, 0.f);
                    float v1 = fmaxf(acc[m][t][1] + bb2, 0.f);
                    float v2 = fmaxf(acc[m][t][2] + ba, 0.f);
                    float v3 = fmaxf(acc[m][t][3] + bb2, 0.f);
                    *(uint32_t*)(sA2 + r * 144 + col * 2) = f2h2(v0, v1);
                    *(uint32_t*)(sA2 + (r + 8) * 144 + col * 2) = f2h2(v2, v3);
                }
            }
        }
        __syncthreads();

        // ---- Layer 2: 64 -> 64 (4 k-steps) --------------------------------
        {
            float acc[2][2][4];
            #pragma unroll
            for (int m = 0; m < 2; ++m)
                #pragma unroll
                for (int t = 0; t < 2; ++t)
                    #pragma unroll
                    for (int e = 0; e < 4; ++e) acc[m][t][e] = 0.f;
            #pragma unroll
            for (int s = 0; s < 4; ++s) {
                uint32_t a[2][4];
                ldm4(a[0][0], a[0][1], a[0][2], a[0][3], a2B + s * 32);
                ldm4(a[1][0], a[1][1], a[1][2], a[1][3], a2B + s * 32 + 16 * 144);
                #pragma unroll
                for (int t = 0; t < 2; ++t) {
                    const uint32_t* bb = sW2u + ((s * 8 + warpN * 2 + t) * 32 + lane) * 2;
                    uint32_t b0 = bb[0], b1v = bb[1];
                    mma16(acc[0][t][0], acc[0][t][1], acc[0][t][2], acc[0][t][3],
                          a[0][0], a[0][1], a[0][2], a[0][3], b0, b1v);
                    mma16(acc[1][t][0], acc[1][t][1], acc[1][t][2], acc[1][t][3],
                          a[1][0], a[1][1], a[1][2], a[1][3], b0, b1v);
                }
            }
            #pragma unroll
            for (int t = 0; t < 2; ++t) {
                int col = (warpN * 2 + t) * 8 + tg * 2;
                float ba = sB2[col], bb2 = sB2[col + 1];
                #pragma unroll
                for (int m = 0; m < 2; ++m) {
                    int r = warpM * 32 + m * 16 + g4;
                    *(float2*)&sL2[r * 68 + col] =
                        make_float2(fmaxf(acc[m][t][0] + ba, 0.f),
                                    fmaxf(acc[m][t][1] + bb2, 0.f));
                    *(float2*)&sL2[(r + 8) * 68 + col] =
                        make_float2(fmaxf(acc[m][t][2] + ba, 0.f),
                                    fmaxf(acc[m][t][3] + bb2, 0.f));
                }
            }
        }
        __syncthreads();

        // ---- Layer 3: 64 -> 1 ---------------------------------------------
        // sL2 is next written only after 2 more barriers (next slab's L2
        // epilogue); sA1 rewrite is fenced by the sync after the next staging.
        if (tid < 64) {
            int grow = row0 + tid;
            if (grow < N) {
                float a = b3[0];
                #pragma unroll
                for (int k = 0; k < 64; ++k) a += sL2[tid * 68 + k] * sW3[k];
                out[grow] = a;
            }
        }
        __syncthreads();
    }
}

// ---------------------------------------------------------------------------
extern "C" void kernel_launch(void* const* d_in, const int* in_sizes, int n_in,
                              void* d_out, int out_size)
{
    const float* x   = (const float*)d_in[0];
    const float* h   = (const float*)d_in[3];
    const float* c   = (const float*)d_in[4];
    const float* Wi  = (const float*)d_in[5];
    const float* Wf  = (const float*)d_in[6];
    const float* Wc  = (const float*)d_in[7];
    const float* Wo  = (const float*)d_in[8];
    const float* Ci  = (const float*)d_in[9];
    const float* Cf  = (const float*)d_in[10];
    const float* Cc  = (const float*)d_in[11];
    const float* Co  = (const float*)d_in[12];
    const float* cbi = (const float*)d_in[13];
    const float* cbf = (const float*)d_in[14];
    const float* cbc = (const float*)d_in[15];
    const float* cbo = (const float*)d_in[16];
    const float* wci = (const float*)d_in[17];
    const float* wcf = (const float*)d_in[18];
    const float* wco = (const float*)d_in[19];
    const float* bi  = (const float*)d_in[20];
    const float* bf  = (const float*)d_in[21];
    const float* bc  = (const float*)d_in[22];
    const float* bo  = (const float*)d_in[23];
    const float* w1  = (const float*)d_in[24];
    const float* b1  = (const float*)d_in[25];
    const float* w2  = (const float*)d_in[26];
    const float* b2  = (const float*)d_in[27];
    const float* w3  = (const float*)d_in[28];
    const float* b3  = (const float*)d_in[29];

    const int N = in_sizes[3] / 128;
    const int nSlab = (N + 63) / 64;

    float* out  = (float*)d_out;
    float* outh = out + N;
    float* outc = outh + (size_t)N * 128;

    pack_kernel<<<(74240 + 8192 + 4096 + 255) / 256, 256>>>(
        Wi, Wf, Wc, Wo, Ci, Cf, Cc, Co,
        cbi, cbf, cbc, cbo, bi, bf, bc, bo, w1, w2);

    cudaFuncSetAttribute(gates_mma,
                         cudaFuncAttributeMaxDynamicSharedMemorySize,
                         GATES_SMEM_BYTES);
    gates_mma<<<296, 256, GATES_SMEM_BYTES>>>(
        x, h, c, wci, wcf, wco, outh, outc, N, nSlab);

    cudaFuncSetAttribute(mlp_mma,
                         cudaFuncAttributeMaxDynamicSharedMemorySize,
                         MLP_SMEM_BYTES);
    mlp_mma<<<296, 256, MLP_SMEM_BYTES>>>(
        outh, b1, b2, w3, b3, out, N, nSlab);
}